// round 1
// baseline (speedup 1.0000x reference)
#include <cuda_runtime.h>
#include <math_constants.h>

// ---------------------------------------------------------------------------
// AffineChamferLoss: bidirectional chamfer between pts_fixed [16384,3] and
// affine-transformed pts_mov [16384,3].
//
// d2_min(q) = ||q||^2 + min_j (||t_j||^2 - 2 q.t_j)
//           = -2*w_q - 2*max_j (q . t_j + w_t),   w = -0.5*||.||^2
//
// Brute-force 16384x16384 both directions, fma.rn.f32x2 inner loop,
// SoA smem target tiles with broadcast LDS, order-preserving-uint atomicMax
// for cross-block max combine, then a mean-reduce finalize.
// ---------------------------------------------------------------------------

#define NMAX 16384
#define TC   2048      // targets per smem chunk
#define BQ   128       // threads per NN block
#define QPT  8         // queries per thread -> 1024 queries per block

typedef unsigned long long u64t;

__device__ float4   g_xbuf[NMAX];   // transformed moving pts: x,y,z, -0.5*||p||^2
__device__ float4   g_ybuf[NMAX];   // fixed pts:              x,y,z, -0.5*||p||^2
__device__ unsigned g_ordA[NMAX];   // ordered-uint running max for dir mov->fix
__device__ unsigned g_ordB[NMAX];   // ordered-uint running max for dir fix->mov

// ---- packed f32x2 helpers --------------------------------------------------
__device__ __forceinline__ u64t pk2(float lo, float hi) {
    u64t r; asm("mov.b64 %0, {%1, %2};" : "=l"(r) : "f"(lo), "f"(hi)); return r;
}
__device__ __forceinline__ u64t fma2(u64t a, u64t b, u64t c) {
    u64t d; asm("fma.rn.f32x2 %0, %1, %2, %3;" : "=l"(d) : "l"(a), "l"(b), "l"(c));
    return d;
}
__device__ __forceinline__ float hmax2(u64t s) {
    float lo, hi; asm("mov.b64 {%0, %1}, %2;" : "=f"(lo), "=f"(hi) : "l"(s));
    return fmaxf(lo, hi);
}

// ---- order-preserving float<->uint (for atomicMax over signed floats) ------
__device__ __forceinline__ unsigned f2ord(float f) {
    unsigned u = __float_as_uint(f);
    return (u & 0x80000000u) ? ~u : (u | 0x80000000u);
}
__device__ __forceinline__ float ord2f(unsigned u) {
    return (u & 0x80000000u) ? __uint_as_float(u & 0x7fffffffu)
                             : __uint_as_float(~u);
}

// ---------------------------------------------------------------------------
__global__ void init_kernel(float* out, int n) {
    int i = blockIdx.x * blockDim.x + threadIdx.x;
    if (i == 0) out[0] = 0.0f;
    if (i < n) { g_ordA[i] = 0u; g_ordB[i] = 0u; }
}

// Affine-transform moving points, pack both sets as float4 {x,y,z,-0.5*n2}
__global__ void prep_kernel(const float* __restrict__ fx,
                            const float* __restrict__ mv,
                            const float* __restrict__ mat,
                            const float* __restrict__ tr,
                            int nf, int nm) {
    int i = blockIdx.x * blockDim.x + threadIdx.x;
    if (i < nm) {
        float p0 = mv[3*i+0], p1 = mv[3*i+1], p2 = mv[3*i+2];
        float x0 = fmaf(p2, mat[6], fmaf(p1, mat[3], fmaf(p0, mat[0], tr[0])));
        float x1 = fmaf(p2, mat[7], fmaf(p1, mat[4], fmaf(p0, mat[1], tr[1])));
        float x2 = fmaf(p2, mat[8], fmaf(p1, mat[5], fmaf(p0, mat[2], tr[2])));
        float n2 = x0*x0 + x1*x1 + x2*x2;
        g_xbuf[i] = make_float4(x0, x1, x2, -0.5f * n2);
    }
    if (i < nf) {
        float y0 = fx[3*i+0], y1 = fx[3*i+1], y2 = fx[3*i+2];
        float n2 = y0*y0 + y1*y1 + y2*y2;
        g_ybuf[i] = make_float4(y0, y1, y2, -0.5f * n2);
    }
}

// NN max kernel: grid (qblocks, tchunks, 2 directions)
__global__ void __launch_bounds__(BQ)
nn_kernel(int nx, int ny) {
    const int dir = blockIdx.z;
    const float4* __restrict__ qb  = dir ? g_ybuf : g_xbuf;
    const float4* __restrict__ tb  = dir ? g_xbuf : g_ybuf;
    unsigned*     __restrict__ ord = dir ? g_ordB : g_ordA;
    const int nq = dir ? ny : nx;
    const int nt = dir ? nx : ny;

    __shared__ __align__(16) float s0[TC];
    __shared__ __align__(16) float s1[TC];
    __shared__ __align__(16) float s2[TC];
    __shared__ __align__(16) float sw[TC];

    const int tstart = blockIdx.y * TC;
    for (int k = threadIdx.x; k < TC; k += BQ) {
        int ti = tstart + k;
        float4 t = (ti < nt) ? tb[ti] : make_float4(0.f, 0.f, 0.f, -3e38f);
        s0[k] = t.x; s1[k] = t.y; s2[k] = t.z; sw[k] = t.w;
    }
    __syncthreads();

    const int qbase = blockIdx.x * (BQ * QPT) + threadIdx.x;
    u64t qx[QPT], qy[QPT], qz[QPT];
    float m[QPT];
#pragma unroll
    for (int q = 0; q < QPT; q++) {
        int qi = qbase + q * BQ;
        float4 v = qb[qi < nq ? qi : 0];
        qx[q] = pk2(v.x, v.x);
        qy[q] = pk2(v.y, v.y);
        qz[q] = pk2(v.z, v.z);
        m[q]  = -CUDART_INF_F;
    }

#pragma unroll 2
    for (int jj = 0; jj < TC; jj += 4) {
        // 4 targets, SoA, each ulonglong2 = two f32x2 halves (broadcast LDS.128)
        ulonglong2 t0 = *reinterpret_cast<const ulonglong2*>(s0 + jj);
        ulonglong2 t1 = *reinterpret_cast<const ulonglong2*>(s1 + jj);
        ulonglong2 t2 = *reinterpret_cast<const ulonglong2*>(s2 + jj);
        ulonglong2 tw = *reinterpret_cast<const ulonglong2*>(sw + jj);
#pragma unroll
        for (int q = 0; q < QPT; q++) {
            u64t sA = fma2(qx[q], t0.x, fma2(qy[q], t1.x, fma2(qz[q], t2.x, tw.x)));
            u64t sB = fma2(qx[q], t0.y, fma2(qy[q], t1.y, fma2(qz[q], t2.y, tw.y)));
            m[q] = fmaxf(m[q], fmaxf(hmax2(sA), hmax2(sB)));
        }
    }

#pragma unroll
    for (int q = 0; q < QPT; q++) {
        int qi = qbase + q * BQ;
        if (qi < nq) atomicMax(&ord[qi], f2ord(m[q]));
    }
}

// Decode maxima, compute clamped d2, mean over each direction, sum into out[0]
__global__ void fin_kernel(float* out, int nx, int ny) {
    int i = blockIdx.x * blockDim.x + threadIdx.x;
    float v = 0.0f;
    if (i < nx) {
        float mm = ord2f(g_ordA[i]);
        float d2 = fmaxf(-2.0f * (g_xbuf[i].w + mm), 0.0f);
        v = d2 / (float)nx;
    } else if (i < nx + ny) {
        int j = i - nx;
        float mm = ord2f(g_ordB[j]);
        float d2 = fmaxf(-2.0f * (g_ybuf[j].w + mm), 0.0f);
        v = d2 / (float)ny;
    }
#pragma unroll
    for (int o = 16; o; o >>= 1) v += __shfl_down_sync(0xffffffffu, v, o);
    __shared__ float ws[32];
    int lane = threadIdx.x & 31, warp = threadIdx.x >> 5;
    if (lane == 0) ws[warp] = v;
    __syncthreads();
    if (warp == 0) {
        v = (lane < (int)(blockDim.x >> 5)) ? ws[lane] : 0.0f;
#pragma unroll
        for (int o = 16; o; o >>= 1) v += __shfl_down_sync(0xffffffffu, v, o);
        if (lane == 0) atomicAdd(out, v);
    }
}

// ---------------------------------------------------------------------------
extern "C" void kernel_launch(void* const* d_in, const int* in_sizes, int n_in,
                              void* d_out, int out_size) {
    const float* fx  = (const float*)d_in[0];  // pts_fixed [N_FIX,3]
    const float* mv  = (const float*)d_in[1];  // pts_mov   [N_MOV,3]
    const float* mat = (const float*)d_in[2];  // [1,3,3]
    const float* tr  = (const float*)d_in[3];  // [1,3,1]
    float* out = (float*)d_out;

    int nf = in_sizes[0] / 3;
    int nm = in_sizes[1] / 3;
    int nmax = nf > nm ? nf : nm;

    init_kernel<<<(nmax + 255) / 256, 256>>>(out, nmax);
    prep_kernel<<<(nmax + 255) / 256, 256>>>(fx, mv, mat, tr, nf, nm);

    dim3 grid((nmax + BQ * QPT - 1) / (BQ * QPT),
              (nmax + TC - 1) / TC,
              2);
    nn_kernel<<<grid, BQ>>>(nm, nf);

    fin_kernel<<<(nf + nm + 255) / 256, 256>>>(out, nm, nf);
}